// round 1
// baseline (speedup 1.0000x reference)
#include <cuda_runtime.h>
#include <cuda_bf16.h>
#include <math.h>

// Problem constants (fixed by the dataset)
#define BATCH 8
#define SEQ   2048
#define CDIM  2048
#define NHEAD 32
#define HSIZE 64
#define MROWS (BATCH*SEQ)          // 16384

static const long long MT = (long long)MROWS * CDIM;  // 33,554,432 elements

// Scratch buffers (device globals — no runtime allocation allowed)
__device__ float g_xn [(size_t)MROWS * CDIM];
__device__ float g_tmp[(size_t)MROWS * CDIM];
__device__ float g_w  [(size_t)MROWS * CDIM];
__device__ float g_k  [(size_t)MROWS * CDIM];
__device__ float g_v  [(size_t)MROWS * CDIM];
__device__ float g_r  [(size_t)MROWS * CDIM];
__device__ float g_y  [(size_t)MROWS * CDIM];

// ---------------------------------------------------------------------------
// LayerNorm: one block per row of C=2048, 256 threads, 8 elems/thread.
// ---------------------------------------------------------------------------
__global__ void ln_kernel(const float* __restrict__ x,
                          const float* __restrict__ gamma,
                          const float* __restrict__ beta,
                          float* __restrict__ out)
{
    const int row = blockIdx.x;
    const int tid = threadIdx.x;
    const float* xr = x + (size_t)row * CDIM;
    float*       orow = out + (size_t)row * CDIM;

    // two float4 loads per thread: [tid*4] and [1024 + tid*4]
    float4 a = *(const float4*)(xr + tid * 4);
    float4 b = *(const float4*)(xr + 1024 + tid * 4);

    float s  = a.x + a.y + a.z + a.w + b.x + b.y + b.z + b.w;
    float sq = a.x*a.x + a.y*a.y + a.z*a.z + a.w*a.w
             + b.x*b.x + b.y*b.y + b.z*b.z + b.w*b.w;

    __shared__ float red[2][32];
    #pragma unroll
    for (int o = 16; o > 0; o >>= 1) {
        s  += __shfl_down_sync(0xffffffffu, s,  o);
        sq += __shfl_down_sync(0xffffffffu, sq, o);
    }
    int wid = tid >> 5, lane = tid & 31;
    if (lane == 0) { red[0][wid] = s; red[1][wid] = sq; }
    __syncthreads();
    if (wid == 0) {
        float ss = (lane < 8) ? red[0][lane] : 0.0f;
        float qq = (lane < 8) ? red[1][lane] : 0.0f;
        #pragma unroll
        for (int o = 4; o > 0; o >>= 1) {
            ss += __shfl_down_sync(0xffffffffu, ss, o);
            qq += __shfl_down_sync(0xffffffffu, qq, o);
        }
        if (lane == 0) { red[0][0] = ss; red[1][0] = qq; }
    }
    __syncthreads();
    float mean = red[0][0] * (1.0f / CDIM);
    float var  = red[1][0] * (1.0f / CDIM) - mean * mean;
    float rstd = rsqrtf(var + 1e-5f);

    float4 g0 = *(const float4*)(gamma + tid * 4);
    float4 g1 = *(const float4*)(gamma + 1024 + tid * 4);
    float4 be0 = *(const float4*)(beta + tid * 4);
    float4 be1 = *(const float4*)(beta + 1024 + tid * 4);

    float4 o0, o1;
    o0.x = (a.x - mean) * rstd * g0.x + be0.x;
    o0.y = (a.y - mean) * rstd * g0.y + be0.y;
    o0.z = (a.z - mean) * rstd * g0.z + be0.z;
    o0.w = (a.w - mean) * rstd * g0.w + be0.w;
    o1.x = (b.x - mean) * rstd * g1.x + be1.x;
    o1.y = (b.y - mean) * rstd * g1.y + be1.y;
    o1.z = (b.z - mean) * rstd * g1.z + be1.z;
    o1.w = (b.w - mean) * rstd * g1.w + be1.w;

    *(float4*)(orow + tid * 4)        = o0;
    *(float4*)(orow + 1024 + tid * 4) = o1;
}

// ---------------------------------------------------------------------------
// SGEMM: C[M,N] = A[M,K] @ B[K,N]; optional bias + sigmoid epilogue.
// 128x128 block tile, BK=8, 256 threads, 8x8 per-thread microtile.
// EPI: 0 = none, 1 = sigmoid, 2 = bias + sigmoid
// ---------------------------------------------------------------------------
template<int EPI>
__global__ __launch_bounds__(256, 2)
void sgemm_kernel(const float* __restrict__ A, const float* __restrict__ B,
                  const float* __restrict__ bias, float* __restrict__ C,
                  int M, int N, int K)
{
    const int BM = 128, BN = 128, BK = 8;
    __shared__ float As[BK][BM];
    __shared__ float Bs[BK][BN];

    const int tid = threadIdx.x;
    const int bx = blockIdx.x;   // N tile
    const int by = blockIdx.y;   // M tile

    const int tcol = tid & 15;   // 0..15
    const int trow = tid >> 4;   // 0..15

    float acc[8][8];
    #pragma unroll
    for (int i = 0; i < 8; i++)
        #pragma unroll
        for (int j = 0; j < 8; j++) acc[i][j] = 0.0f;

    const int aRow = tid >> 1;          // 0..127
    const int aCol = (tid & 1) * 4;     // 0 or 4
    const int bRow = tid >> 5;          // 0..7
    const int bCol = (tid & 31) * 4;    // 0..124

    const float* Ablk = A + (size_t)(by * BM) * K;
    const float* Bblk = B + (size_t)bx * BN;

    for (int k0 = 0; k0 < K; k0 += BK) {
        float4 a4 = *(const float4*)(Ablk + (size_t)aRow * K + k0 + aCol);
        As[aCol + 0][aRow] = a4.x;
        As[aCol + 1][aRow] = a4.y;
        As[aCol + 2][aRow] = a4.z;
        As[aCol + 3][aRow] = a4.w;
        float4 b4 = *(const float4*)(Bblk + (size_t)(k0 + bRow) * N + bCol);
        *(float4*)&Bs[bRow][bCol] = b4;
        __syncthreads();

        #pragma unroll
        for (int kk = 0; kk < BK; kk++) {
            float4 ra0 = *(const float4*)&As[kk][trow * 8];
            float4 ra1 = *(const float4*)&As[kk][trow * 8 + 4];
            float4 rb0 = *(const float4*)&Bs[kk][tcol * 8];
            float4 rb1 = *(const float4*)&Bs[kk][tcol * 8 + 4];
            float ra[8] = {ra0.x, ra0.y, ra0.z, ra0.w, ra1.x, ra1.y, ra1.z, ra1.w};
            float rb[8] = {rb0.x, rb0.y, rb0.z, rb0.w, rb1.x, rb1.y, rb1.z, rb1.w};
            #pragma unroll
            for (int i = 0; i < 8; i++)
                #pragma unroll
                for (int j = 0; j < 8; j++)
                    acc[i][j] = fmaf(ra[i], rb[j], acc[i][j]);
        }
        __syncthreads();
    }

    const int crow0 = by * BM + trow * 8;
    const int ccol0 = bx * BN + tcol * 8;

    float bvals[8];
    if (EPI == 2) {
        #pragma unroll
        for (int j = 0; j < 8; j++) bvals[j] = bias[ccol0 + j];
    }

    #pragma unroll
    for (int i = 0; i < 8; i++) {
        float vr[8];
        #pragma unroll
        for (int j = 0; j < 8; j++) {
            float c = acc[i][j];
            if (EPI == 2) c += bvals[j];
            if (EPI >= 1) c = 1.0f / (1.0f + expf(-c));
            vr[j] = c;
        }
        float* crow = C + (size_t)(crow0 + i) * N + ccol0;
        *(float4*)(crow)     = make_float4(vr[0], vr[1], vr[2], vr[3]);
        *(float4*)(crow + 4) = make_float4(vr[4], vr[5], vr[6], vr[7]);
    }
}

// ---------------------------------------------------------------------------
// Selective WKV scan. One block per (b,h) pair; 256 threads.
// Thread (q, j): q = tid>>6 (row quarter, 16 rows), j = tid&63 (state column).
// state[i][j] = (1 - w[i]) * state[i][j] + k[i] * v[j];  y[j] = sum_i r[i]*state[i][j]
// Double-buffered SMEM for per-step vectors with register prefetch of step t+1.
// ---------------------------------------------------------------------------
__global__ __launch_bounds__(256, 4)
void scan_kernel(const float* __restrict__ w, const float* __restrict__ k,
                 const float* __restrict__ v, const float* __restrict__ r,
                 float* __restrict__ y, float* __restrict__ state_out)
{
    const int bh = blockIdx.x;
    const int b  = bh / NHEAD;
    const int h  = bh % NHEAD;
    const int tid = threadIdx.x;
    const int j   = tid & 63;
    const int q   = tid >> 6;

    __shared__ float sh[2][4][64];   // [buf][w/k/v/r][lane]
    __shared__ float ysh[4][64];

    const size_t base = ((size_t)b * SEQ) * CDIM + (size_t)h * HSIZE;

    const int vec = q;                // which vector this 64-thread group loads
    const int lane = j;
    const float* pvec = (vec == 0) ? w : (vec == 1) ? k : (vec == 2) ? v : r;

    // prefetch t = 0
    sh[0][vec][lane] = pvec[base + lane];

    float st[16];
    #pragma unroll
    for (int ii = 0; ii < 16; ii++) st[ii] = 0.0f;

    __syncthreads();

    for (int t = 0; t < SEQ; t++) {
        const int cur = t & 1;
        // issue prefetch for t+1 early (independent of compute)
        float pf = 0.0f;
        if (t + 1 < SEQ) pf = pvec[base + (size_t)(t + 1) * CDIM + lane];

        const float vj = sh[cur][2][j];
        float acc = 0.0f;
        #pragma unroll
        for (int ii = 0; ii < 16; ii++) {
            const int i = q * 16 + ii;
            const float wi = sh[cur][0][i];
            const float ki = sh[cur][1][i];
            const float ri = sh[cur][3][i];
            float s = st[ii];
            s = (1.0f - wi) * s + ki * vj;
            st[ii] = s;
            acc = fmaf(ri, s, acc);
        }
        ysh[q][j] = acc;
        __syncthreads();

        sh[cur ^ 1][vec][lane] = pf;
        if (q == 0) {
            float yv = ysh[0][j] + ysh[1][j] + ysh[2][j] + ysh[3][j];
            y[base + (size_t)t * CDIM + j] = yv;
        }
        __syncthreads();
    }

    if (state_out != nullptr) {
        #pragma unroll
        for (int ii = 0; ii < 16; ii++) {
            const int i = q * 16 + ii;
            state_out[(((size_t)b * NHEAD + h) * HSIZE + i) * HSIZE + j] = st[ii];
        }
    }
}

// ---------------------------------------------------------------------------
// Launch
// ---------------------------------------------------------------------------
extern "C" void kernel_launch(void* const* d_in, const int* in_sizes, int n_in,
                              void* d_out, int out_size)
{
    const float* x     = (const float*)d_in[0];
    const float* Wx    = (const float*)d_in[1];
    const float* Ww    = (const float*)d_in[2];
    const float* bw    = (const float*)d_in[3];
    const float* Wk    = (const float*)d_in[4];
    const float* Wv    = (const float*)d_in[5];
    const float* Wr    = (const float*)d_in[6];
    const float* Wo    = (const float*)d_in[7];
    const float* gamma = (const float*)d_in[8];
    const float* beta  = (const float*)d_in[9];
    float* out = (float*)d_out;

    float *xn, *tmp, *w, *k, *v, *r, *y;
    cudaGetSymbolAddress((void**)&xn,  g_xn);
    cudaGetSymbolAddress((void**)&tmp, g_tmp);
    cudaGetSymbolAddress((void**)&w,   g_w);
    cudaGetSymbolAddress((void**)&k,   g_k);
    cudaGetSymbolAddress((void**)&v,   g_v);
    cudaGetSymbolAddress((void**)&r,   g_r);
    cudaGetSymbolAddress((void**)&y,   g_y);

    const int M = MROWS, N = CDIM, K = CDIM;
    dim3 gg(N / 128, M / 128);
    dim3 bb(256);

    // 1. LayerNorm
    ln_kernel<<<MROWS, 256>>>(x, gamma, beta, xn);

    // 2. Projections
    sgemm_kernel<0><<<gg, bb>>>(xn,  Wx, nullptr, tmp, M, N, K);
    sgemm_kernel<2><<<gg, bb>>>(tmp, Ww, bw,      w,   M, N, K);
    sgemm_kernel<0><<<gg, bb>>>(xn,  Wk, nullptr, k,   M, N, K);
    sgemm_kernel<0><<<gg, bb>>>(xn,  Wv, nullptr, v,   M, N, K);
    sgemm_kernel<1><<<gg, bb>>>(xn,  Wr, nullptr, r,   M, N, K);

    // 3. Recurrent scan (writes y; optionally final state into tail of d_out)
    long long n_y = (long long)MROWS * CDIM;
    float* state_ptr = ((long long)out_size > n_y) ? (out + n_y) : nullptr;
    scan_kernel<<<BATCH * NHEAD, 256>>>(w, k, v, r, y, state_ptr);

    // 4. Output projection
    sgemm_kernel<0><<<gg, bb>>>(y, Wo, nullptr, out, M, N, K);
}

// round 5
// speedup vs baseline: 1.3359x; 1.3359x over previous
#include <cuda_runtime.h>
#include <cuda_bf16.h>
#include <mma.h>
#include <math.h>
#include <stdint.h>

using namespace nvcuda;

#define BATCH 8
#define SEQ   2048
#define CDIM  2048
#define NHEAD 32
#define HSIZE 64
#define MROWS (BATCH*SEQ)          // 16384

// Scratch buffers (device globals — no runtime allocation allowed)
__device__ float g_xn [(size_t)MROWS * CDIM];
__device__ float g_tmp[(size_t)MROWS * CDIM];
__device__ float g_w  [(size_t)MROWS * CDIM];
__device__ float g_k  [(size_t)MROWS * CDIM];
__device__ float g_v  [(size_t)MROWS * CDIM];
__device__ float g_r  [(size_t)MROWS * CDIM];
__device__ float g_y  [(size_t)MROWS * CDIM];

// ---------------------------------------------------------------------------
// cp.async helpers (baseline sm_80 PTX — compiles for plain sm_103 target)
// ---------------------------------------------------------------------------
__device__ __forceinline__ uint32_t smem_u32(const void* p) {
    return (uint32_t)__cvta_generic_to_shared(p);
}
__device__ __forceinline__ void cp_async16(uint32_t smem, const void* gmem) {
    asm volatile("cp.async.cg.shared.global [%0], [%1], 16;" :: "r"(smem), "l"(gmem) : "memory");
}
#define CP_COMMIT() asm volatile("cp.async.commit_group;" ::: "memory")
#define CP_WAIT2()  asm volatile("cp.async.wait_group 2;"  ::: "memory")

// ---------------------------------------------------------------------------
// LayerNorm: one block per row of C=2048, 256 threads (full fp32 output).
// ---------------------------------------------------------------------------
__global__ void ln_kernel(const float* __restrict__ x,
                          const float* __restrict__ gamma,
                          const float* __restrict__ beta,
                          float* __restrict__ out)
{
    const int row = blockIdx.x;
    const int tid = threadIdx.x;
    const float* xr = x + (size_t)row * CDIM;
    float* orow = out + (size_t)row * CDIM;

    float4 a = *(const float4*)(xr + tid * 4);
    float4 b = *(const float4*)(xr + 1024 + tid * 4);

    float s  = a.x + a.y + a.z + a.w + b.x + b.y + b.z + b.w;
    float sq = a.x*a.x + a.y*a.y + a.z*a.z + a.w*a.w
             + b.x*b.x + b.y*b.y + b.z*b.z + b.w*b.w;

    __shared__ float red[2][32];
    #pragma unroll
    for (int o = 16; o > 0; o >>= 1) {
        s  += __shfl_down_sync(0xffffffffu, s,  o);
        sq += __shfl_down_sync(0xffffffffu, sq, o);
    }
    int wid = tid >> 5, lane = tid & 31;
    if (lane == 0) { red[0][wid] = s; red[1][wid] = sq; }
    __syncthreads();
    if (wid == 0) {
        float ss = (lane < 8) ? red[0][lane] : 0.0f;
        float qq = (lane < 8) ? red[1][lane] : 0.0f;
        #pragma unroll
        for (int o = 4; o > 0; o >>= 1) {
            ss += __shfl_down_sync(0xffffffffu, ss, o);
            qq += __shfl_down_sync(0xffffffffu, qq, o);
        }
        if (lane == 0) { red[0][0] = ss; red[1][0] = qq; }
    }
    __syncthreads();
    float mean = red[0][0] * (1.0f / CDIM);
    float var  = red[1][0] * (1.0f / CDIM) - mean * mean;
    float rstd = rsqrtf(var + 1e-5f);

    float4 g0 = *(const float4*)(gamma + tid * 4);
    float4 g1 = *(const float4*)(gamma + 1024 + tid * 4);
    float4 be0 = *(const float4*)(beta + tid * 4);
    float4 be1 = *(const float4*)(beta + 1024 + tid * 4);

    float4 o0, o1;
    o0.x = (a.x - mean) * rstd * g0.x + be0.x;
    o0.y = (a.y - mean) * rstd * g0.y + be0.y;
    o0.z = (a.z - mean) * rstd * g0.z + be0.z;
    o0.w = (a.w - mean) * rstd * g0.w + be0.w;
    o1.x = (b.x - mean) * rstd * g1.x + be1.x;
    o1.y = (b.y - mean) * rstd * g1.y + be1.y;
    o1.z = (b.z - mean) * rstd * g1.z + be1.z;
    o1.w = (b.w - mean) * rstd * g1.w + be1.w;

    *(float4*)(orow + tid * 4)        = o0;
    *(float4*)(orow + 1024 + tid * 4) = o1;
}

// ---------------------------------------------------------------------------
// WMMA TF32 GEMM: C[M,N] = A[M,K] @ B[K,N]   (B = weight, native layout!)
// BM=128, BN=128, BK=16, 4-stage cp.async pipeline.
// 8 warps: 4 (m) x 2 (n); warp tile 32x64 = 2x4 wmma m16n16k8 tiles.
// EPI: 0=none, 1=sigmoid, 2=bias+sigmoid
// ---------------------------------------------------------------------------
#define BM 128
#define BN 128
#define BK 16
#define NSTAGE 4
#define A_LD 20            // 16 + 4 pad (keeps rows 16B aligned)
#define B_LD 132           // 128 + 4 pad
#define A_FLOATS (BM * A_LD)          // 2560
#define B_FLOATS (BK * B_LD)          // 2112
#define STAGE_FLOATS (A_FLOATS + B_FLOATS)  // 4672
#define SMEM_FLOATS (NSTAGE * STAGE_FLOATS) // 18688
#define C_LD 132
#define SMEM_BYTES ((SMEM_FLOATS > BM * C_LD ? SMEM_FLOATS : BM * C_LD) * 4)

template<int EPI>
__global__ void __launch_bounds__(256, 1)
gemm_wmma(const float* __restrict__ A, const float* __restrict__ B,
          const float* __restrict__ bias, float* __restrict__ C,
          int M, int N, int K)
{
    extern __shared__ float smem[];
    const int tid = threadIdx.x;
    const int wid = tid >> 5;
    const int bx = blockIdx.x;   // N tile
    const int by = blockIdx.y;   // M tile
    const int NITER = K / BK;    // 128

    const int wm = wid & 3;      // warp row: 0..3 -> 32-row slabs
    const int wn = wid >> 2;     // warp col: 0..1 -> 64-col slabs

    const float* Ablk = A + (size_t)(by * BM) * K;
    const float* Bblk = B + (size_t)(bx * BN);

    // per-thread load coordinates (2 A chunks + 2 B chunks of 16B per stage)
    const int ar0 = tid >> 2, ac0 = (tid & 3) * 4;          // chunks 0..255
    const int ar1 = (tid + 256) >> 2, ac1 = (tid & 3) * 4;  // chunks 256..511
    const int br0 = tid >> 5, bc0 = (tid & 31) * 4;
    const int br1 = (tid + 256) >> 5, bc1 = (tid & 31) * 4;

    const uint32_t smem_b = smem_u32(smem);

    auto load_stage = [&](int s, int k0) {
        const uint32_t as = smem_b + (uint32_t)(s * STAGE_FLOATS) * 4;
        const uint32_t bs = as + (uint32_t)A_FLOATS * 4;
        cp_async16(as + (uint32_t)(ar0 * A_LD + ac0) * 4, Ablk + (size_t)ar0 * K + k0 + ac0);
        cp_async16(as + (uint32_t)(ar1 * A_LD + ac1) * 4, Ablk + (size_t)ar1 * K + k0 + ac1);
        cp_async16(bs + (uint32_t)(br0 * B_LD + bc0) * 4, Bblk + (size_t)(k0 + br0) * N + bc0);
        cp_async16(bs + (uint32_t)(br1 * B_LD + bc1) * 4, Bblk + (size_t)(k0 + br1) * N + bc1);
    };

    wmma::fragment<wmma::accumulator, 16, 16, 8, float> acc[2][4];
    #pragma unroll
    for (int mi = 0; mi < 2; mi++)
        #pragma unroll
        for (int ni = 0; ni < 4; ni++)
            wmma::fill_fragment(acc[mi][ni], 0.0f);

    // prologue: stages 0..2
    #pragma unroll
    for (int j = 0; j < NSTAGE - 1; j++) { load_stage(j, j * BK); CP_COMMIT(); }

    for (int i = 0; i < NITER; i++) {
        CP_WAIT2();
        __syncthreads();

        // prefetch stage i+3 (overwrites slot used by compute of i-1; barrier above protects)
        if (i + NSTAGE - 1 < NITER) load_stage((i + NSTAGE - 1) & (NSTAGE - 1), (i + NSTAGE - 1) * BK);
        CP_COMMIT();

        const int s = i & (NSTAGE - 1);
        const float* As = smem + s * STAGE_FLOATS;
        const float* Bs = As + A_FLOATS;

        #pragma unroll
        for (int ks = 0; ks < 2; ks++) {
            wmma::fragment<wmma::matrix_a, 16, 16, 8, wmma::precision::tf32, wmma::row_major> af[2];
            wmma::fragment<wmma::matrix_b, 16, 16, 8, wmma::precision::tf32, wmma::row_major> bf[4];
            #pragma unroll
            for (int mi = 0; mi < 2; mi++) {
                wmma::load_matrix_sync(af[mi], As + (wm * 32 + mi * 16) * A_LD + ks * 8, A_LD);
                #pragma unroll
                for (int t = 0; t < af[mi].num_elements; t++)
                    af[mi].x[t] = wmma::__float_to_tf32(af[mi].x[t]);
            }
            #pragma unroll
            for (int ni = 0; ni < 4; ni++) {
                wmma::load_matrix_sync(bf[ni], Bs + (ks * 8) * B_LD + wn * 64 + ni * 16, B_LD);
                #pragma unroll
                for (int t = 0; t < bf[ni].num_elements; t++)
                    bf[ni].x[t] = wmma::__float_to_tf32(bf[ni].x[t]);
            }
            #pragma unroll
            for (int mi = 0; mi < 2; mi++)
                #pragma unroll
                for (int ni = 0; ni < 4; ni++)
                    wmma::mma_sync(acc[mi][ni], af[mi], bf[ni], acc[mi][ni]);
        }
    }

    // epilogue: stage accumulators through smem, then vectorized global write
    __syncthreads();
    float* Cs = smem;
    #pragma unroll
    for (int mi = 0; mi < 2; mi++)
        #pragma unroll
        for (int ni = 0; ni < 4; ni++)
            wmma::store_matrix_sync(Cs + (wm * 32 + mi * 16) * C_LD + wn * 64 + ni * 16,
                                    acc[mi][ni], C_LD, wmma::mem_row_major);
    __syncthreads();

    const int n0 = bx * BN;
    #pragma unroll
    for (int it = 0; it < 16; it++) {
        const int idx = tid + it * 256;        // 0..4095
        const int r = idx >> 5;
        const int c4 = (idx & 31) * 4;
        float4 vv = *(const float4*)(Cs + r * C_LD + c4);
        if (EPI == 2) {
            const float4 bb = *(const float4*)(bias + n0 + c4);
            vv.x += bb.x; vv.y += bb.y; vv.z += bb.z; vv.w += bb.w;
        }
        if (EPI >= 1) {
            vv.x = 1.0f / (1.0f + expf(-vv.x));
            vv.y = 1.0f / (1.0f + expf(-vv.y));
            vv.z = 1.0f / (1.0f + expf(-vv.z));
            vv.w = 1.0f / (1.0f + expf(-vv.w));
        }
        *(float4*)(C + (size_t)(by * BM + r) * N + n0 + c4) = vv;
    }
}

// ---------------------------------------------------------------------------
// Selective WKV scan. One block per (b,h) pair; 256 threads.
// ---------------------------------------------------------------------------
__global__ __launch_bounds__(256, 4)
void scan_kernel(const float* __restrict__ w, const float* __restrict__ k,
                 const float* __restrict__ v, const float* __restrict__ r,
                 float* __restrict__ y, float* __restrict__ state_out)
{
    const int bh = blockIdx.x;
    const int b  = bh / NHEAD;
    const int h  = bh % NHEAD;
    const int tid = threadIdx.x;
    const int j   = tid & 63;
    const int q   = tid >> 6;

    __shared__ float sh[2][4][64];
    __shared__ float ysh[4][64];

    const size_t base = ((size_t)b * SEQ) * CDIM + (size_t)h * HSIZE;

    const int vec = q;
    const int lane = j;
    const float* pvec = (vec == 0) ? w : (vec == 1) ? k : (vec == 2) ? v : r;

    sh[0][vec][lane] = pvec[base + lane];

    float st[16];
    #pragma unroll
    for (int ii = 0; ii < 16; ii++) st[ii] = 0.0f;

    __syncthreads();

    for (int t = 0; t < SEQ; t++) {
        const int cur = t & 1;
        float pf = 0.0f;
        if (t + 1 < SEQ) pf = pvec[base + (size_t)(t + 1) * CDIM + lane];

        const float vj = sh[cur][2][j];
        float acc = 0.0f;
        #pragma unroll
        for (int ii = 0; ii < 16; ii++) {
            const int i = q * 16 + ii;
            const float wi = sh[cur][0][i];
            const float ki = sh[cur][1][i];
            const float ri = sh[cur][3][i];
            float s = st[ii];
            s = (1.0f - wi) * s + ki * vj;
            st[ii] = s;
            acc = fmaf(ri, s, acc);
        }
        ysh[q][j] = acc;
        __syncthreads();

        sh[cur ^ 1][vec][lane] = pf;
        if (q == 0) {
            float yv = ysh[0][j] + ysh[1][j] + ysh[2][j] + ysh[3][j];
            y[base + (size_t)t * CDIM + j] = yv;
        }
        __syncthreads();
    }

    if (state_out != nullptr) {
        #pragma unroll
        for (int ii = 0; ii < 16; ii++) {
            const int i = q * 16 + ii;
            state_out[(((size_t)b * NHEAD + h) * HSIZE + i) * HSIZE + j] = st[ii];
        }
    }
}

// ---------------------------------------------------------------------------
// Launch
// ---------------------------------------------------------------------------
extern "C" void kernel_launch(void* const* d_in, const int* in_sizes, int n_in,
                              void* d_out, int out_size)
{
    const float* x     = (const float*)d_in[0];
    const float* Wx    = (const float*)d_in[1];
    const float* Ww    = (const float*)d_in[2];
    const float* bw    = (const float*)d_in[3];
    const float* Wk    = (const float*)d_in[4];
    const float* Wv    = (const float*)d_in[5];
    const float* Wr    = (const float*)d_in[6];
    const float* Wo    = (const float*)d_in[7];
    const float* gamma = (const float*)d_in[8];
    const float* beta  = (const float*)d_in[9];
    float* out = (float*)d_out;

    float *xn, *tmp, *w, *k, *v, *r, *y;
    cudaGetSymbolAddress((void**)&xn,  g_xn);
    cudaGetSymbolAddress((void**)&tmp, g_tmp);
    cudaGetSymbolAddress((void**)&w,   g_w);
    cudaGetSymbolAddress((void**)&k,   g_k);
    cudaGetSymbolAddress((void**)&v,   g_v);
    cudaGetSymbolAddress((void**)&r,   g_r);
    cudaGetSymbolAddress((void**)&y,   g_y);

    cudaFuncSetAttribute(gemm_wmma<0>, cudaFuncAttributeMaxDynamicSharedMemorySize, SMEM_BYTES);
    cudaFuncSetAttribute(gemm_wmma<1>, cudaFuncAttributeMaxDynamicSharedMemorySize, SMEM_BYTES);
    cudaFuncSetAttribute(gemm_wmma<2>, cudaFuncAttributeMaxDynamicSharedMemorySize, SMEM_BYTES);

    const int M = MROWS, N = CDIM, K = CDIM;
    dim3 gg(N / BN, M / BM);   // (16, 128)

    // 1. LayerNorm
    ln_kernel<<<MROWS, 256>>>(x, gamma, beta, xn);

    // 2. Projections (weights used in native [K,N] layout — no transpose)
    gemm_wmma<0><<<gg, 256, SMEM_BYTES>>>(xn,  Wx, nullptr, tmp, M, N, K);
    gemm_wmma<2><<<gg, 256, SMEM_BYTES>>>(tmp, Ww, bw,      w,   M, N, K);
    gemm_wmma<0><<<gg, 256, SMEM_BYTES>>>(xn,  Wk, nullptr, k,   M, N, K);
    gemm_wmma<0><<<gg, 256, SMEM_BYTES>>>(xn,  Wv, nullptr, v,   M, N, K);
    gemm_wmma<1><<<gg, 256, SMEM_BYTES>>>(xn,  Wr, nullptr, r,   M, N, K);

    // 3. Recurrent scan
    long long n_y = (long long)MROWS * CDIM;
    float* state_ptr = ((long long)out_size > n_y) ? (out + n_y) : nullptr;
    scan_kernel<<<BATCH * NHEAD, 256>>>(w, k, v, r, y, state_ptr);

    // 4. Output projection
    gemm_wmma<0><<<gg, 256, SMEM_BYTES>>>(y, Wo, nullptr, out, M, N, K);
}

// round 9
// speedup vs baseline: 1.6161x; 1.2097x over previous
#include <cuda_runtime.h>
#include <cuda_bf16.h>
#include <mma.h>
#include <math.h>
#include <stdint.h>

using namespace nvcuda;

#define BATCH 8
#define SEQ   2048
#define CDIM  2048
#define NHEAD 32
#define HSIZE 64
#define MROWS (BATCH*SEQ)          // 16384

// Scratch buffers (device globals — no runtime allocation allowed)
__device__ float g_xn [(size_t)MROWS * CDIM];
__device__ float g_tmp[(size_t)MROWS * CDIM];
__device__ float g_w  [(size_t)MROWS * CDIM];
__device__ float g_k  [(size_t)MROWS * CDIM];
__device__ float g_v  [(size_t)MROWS * CDIM];
__device__ float g_r  [(size_t)MROWS * CDIM];
__device__ float g_y  [(size_t)MROWS * CDIM];
__device__ float g_wt [(size_t)CDIM * CDIM];   // tf32-rounded weight (reused per GEMM)

// ---------------------------------------------------------------------------
// helpers
// ---------------------------------------------------------------------------
__device__ __forceinline__ uint32_t smem_u32(const void* p) {
    return (uint32_t)__cvta_generic_to_shared(p);
}
__device__ __forceinline__ void cp_async16(uint32_t smem, const void* gmem) {
    asm volatile("cp.async.cg.shared.global [%0], [%1], 16;" :: "r"(smem), "l"(gmem) : "memory");
}
#define CP_COMMIT() asm volatile("cp.async.commit_group;" ::: "memory")
#define CP_WAIT2()  asm volatile("cp.async.wait_group 2;"  ::: "memory")

__device__ __forceinline__ float to_tf32(float f) {
    uint32_t u;
    asm("cvt.rna.tf32.f32 %0, %1;" : "=r"(u) : "f"(f));
    return __uint_as_float(u);
}

// ---------------------------------------------------------------------------
// Round a tensor to tf32 in-memory (weights). 4 elems/thread.
// ---------------------------------------------------------------------------
__global__ void round_tf32_kernel(const float* __restrict__ in, float* __restrict__ out)
{
    const size_t i = ((size_t)blockIdx.x * blockDim.x + threadIdx.x) * 4;
    float4 vv = *(const float4*)(in + i);
    vv.x = to_tf32(vv.x); vv.y = to_tf32(vv.y);
    vv.z = to_tf32(vv.z); vv.w = to_tf32(vv.w);
    *(float4*)(out + i) = vv;
}

// ---------------------------------------------------------------------------
// LayerNorm: one block per row of C=2048, 256 threads. Output tf32-rounded
// (only consumed as GEMM A operand).
// ---------------------------------------------------------------------------
__global__ void ln_kernel(const float* __restrict__ x,
                          const float* __restrict__ gamma,
                          const float* __restrict__ beta,
                          float* __restrict__ out)
{
    const int row = blockIdx.x;
    const int tid = threadIdx.x;
    const float* xr = x + (size_t)row * CDIM;
    float* orow = out + (size_t)row * CDIM;

    float4 a = *(const float4*)(xr + tid * 4);
    float4 b = *(const float4*)(xr + 1024 + tid * 4);

    float s  = a.x + a.y + a.z + a.w + b.x + b.y + b.z + b.w;
    float sq = a.x*a.x + a.y*a.y + a.z*a.z + a.w*a.w
             + b.x*b.x + b.y*b.y + b.z*b.z + b.w*b.w;

    __shared__ float red[2][32];
    #pragma unroll
    for (int o = 16; o > 0; o >>= 1) {
        s  += __shfl_down_sync(0xffffffffu, s,  o);
        sq += __shfl_down_sync(0xffffffffu, sq, o);
    }
    int wid = tid >> 5, lane = tid & 31;
    if (lane == 0) { red[0][wid] = s; red[1][wid] = sq; }
    __syncthreads();
    if (wid == 0) {
        float ss = (lane < 8) ? red[0][lane] : 0.0f;
        float qq = (lane < 8) ? red[1][lane] : 0.0f;
        #pragma unroll
        for (int o = 4; o > 0; o >>= 1) {
            ss += __shfl_down_sync(0xffffffffu, ss, o);
            qq += __shfl_down_sync(0xffffffffu, qq, o);
        }
        if (lane == 0) { red[0][0] = ss; red[1][0] = qq; }
    }
    __syncthreads();
    float mean = red[0][0] * (1.0f / CDIM);
    float var  = red[1][0] * (1.0f / CDIM) - mean * mean;
    float rstd = rsqrtf(var + 1e-5f);

    float4 g0 = *(const float4*)(gamma + tid * 4);
    float4 g1 = *(const float4*)(gamma + 1024 + tid * 4);
    float4 be0 = *(const float4*)(beta + tid * 4);
    float4 be1 = *(const float4*)(beta + 1024 + tid * 4);

    float4 o0, o1;
    o0.x = to_tf32((a.x - mean) * rstd * g0.x + be0.x);
    o0.y = to_tf32((a.y - mean) * rstd * g0.y + be0.y);
    o0.z = to_tf32((a.z - mean) * rstd * g0.z + be0.z);
    o0.w = to_tf32((a.w - mean) * rstd * g0.w + be0.w);
    o1.x = to_tf32((b.x - mean) * rstd * g1.x + be1.x);
    o1.y = to_tf32((b.y - mean) * rstd * g1.y + be1.y);
    o1.z = to_tf32((b.z - mean) * rstd * g1.z + be1.z);
    o1.w = to_tf32((b.w - mean) * rstd * g1.w + be1.w);

    *(float4*)(orow + tid * 4)        = o0;
    *(float4*)(orow + 1024 + tid * 4) = o1;
}

// ---------------------------------------------------------------------------
// WMMA TF32 GEMM: C[M,N] = A[M,K] @ B[K,N]. Operands PRE-ROUNDED to tf32 in
// memory — no per-fragment cvt in the main loop (HW truncation is identity).
// BM=128, BN=128, BK=16, 4-stage cp.async pipeline, 2 CTAs/SM.
// 8 warps: 4 (m) x 2 (n); warp tile 32x64 = 2x4 wmma m16n16k8 tiles.
// EPI: 0=none, 1=sigmoid, 2=bias+sigmoid (smem-staged), 3=round-to-tf32
// ---------------------------------------------------------------------------
#define BM 128
#define BN 128
#define BK 16
#define NSTAGE 4
#define A_LD 20            // 16 + 4 pad
#define B_LD 132           // 128 + 4 pad
#define A_FLOATS (BM * A_LD)                 // 2560
#define B_FLOATS (BK * B_LD)                 // 2112
#define STAGE_FLOATS (A_FLOATS + B_FLOATS)   // 4672
#define SMEM_FLOATS (NSTAGE * STAGE_FLOATS)  // 18688
#define C_LD 132
#define SMEM_BYTES (SMEM_FLOATS * 4)         // 74752 (> 64*C_LD*4 staging)

template<int EPI>
__global__ void __launch_bounds__(256, 2)
gemm_wmma(const float* __restrict__ A, const float* __restrict__ B,
          const float* __restrict__ bias, float* __restrict__ C,
          int M, int N, int K)
{
    extern __shared__ float smem[];
    const int tid = threadIdx.x;
    const int wid = tid >> 5;
    const int bx = blockIdx.x;   // N tile
    const int by = blockIdx.y;   // M tile
    const int NITER = K / BK;    // 128

    const int wm = wid & 3;      // warp row: 32-row slab
    const int wn = wid >> 2;     // warp col: 64-col slab

    const float* Ablk = A + (size_t)(by * BM) * K;
    const float* Bblk = B + (size_t)(bx * BN);

    const int ar0 = tid >> 2,         ac0 = (tid & 3) * 4;
    const int ar1 = (tid + 256) >> 2, ac1 = (tid & 3) * 4;
    const int br0 = tid >> 5,         bc0 = (tid & 31) * 4;
    const int br1 = (tid + 256) >> 5, bc1 = (tid & 31) * 4;

    const uint32_t smem_b = smem_u32(smem);

    auto load_stage = [&](int s, int k0) {
        const uint32_t as = smem_b + (uint32_t)(s * STAGE_FLOATS) * 4;
        const uint32_t bs = as + (uint32_t)A_FLOATS * 4;
        cp_async16(as + (uint32_t)(ar0 * A_LD + ac0) * 4, Ablk + (size_t)ar0 * K + k0 + ac0);
        cp_async16(as + (uint32_t)(ar1 * A_LD + ac1) * 4, Ablk + (size_t)ar1 * K + k0 + ac1);
        cp_async16(bs + (uint32_t)(br0 * B_LD + bc0) * 4, Bblk + (size_t)(k0 + br0) * N + bc0);
        cp_async16(bs + (uint32_t)(br1 * B_LD + bc1) * 4, Bblk + (size_t)(k0 + br1) * N + bc1);
    };

    wmma::fragment<wmma::accumulator, 16, 16, 8, float> acc[2][4];
    #pragma unroll
    for (int mi = 0; mi < 2; mi++)
        #pragma unroll
        for (int ni = 0; ni < 4; ni++)
            wmma::fill_fragment(acc[mi][ni], 0.0f);

    #pragma unroll
    for (int j = 0; j < NSTAGE - 1; j++) { load_stage(j, j * BK); CP_COMMIT(); }

    for (int i = 0; i < NITER; i++) {
        CP_WAIT2();
        __syncthreads();

        if (i + NSTAGE - 1 < NITER)
            load_stage((i + NSTAGE - 1) & (NSTAGE - 1), (i + NSTAGE - 1) * BK);
        CP_COMMIT();

        const int s = i & (NSTAGE - 1);
        const float* As = smem + s * STAGE_FLOATS;
        const float* Bs = As + A_FLOATS;

        #pragma unroll
        for (int ks = 0; ks < 2; ks++) {
            wmma::fragment<wmma::matrix_a, 16, 16, 8, wmma::precision::tf32, wmma::row_major> af[2];
            wmma::fragment<wmma::matrix_b, 16, 16, 8, wmma::precision::tf32, wmma::row_major> bf[4];
            #pragma unroll
            for (int mi = 0; mi < 2; mi++)
                wmma::load_matrix_sync(af[mi], As + (wm * 32 + mi * 16) * A_LD + ks * 8, A_LD);
            #pragma unroll
            for (int ni = 0; ni < 4; ni++)
                wmma::load_matrix_sync(bf[ni], Bs + (ks * 8) * B_LD + wn * 64 + ni * 16, B_LD);
            // NOTE: operands pre-rounded to tf32 in memory; no cvt needed.
            #pragma unroll
            for (int mi = 0; mi < 2; mi++)
                #pragma unroll
                for (int ni = 0; ni < 4; ni++)
                    wmma::mma_sync(acc[mi][ni], af[mi], bf[ni], acc[mi][ni]);
        }
    }

    if (EPI != 2) {
        // direct-from-fragment epilogue (elementwise ops are position-free)
        #pragma unroll
        for (int mi = 0; mi < 2; mi++) {
            #pragma unroll
            for (int ni = 0; ni < 4; ni++) {
                if (EPI == 1) {
                    #pragma unroll
                    for (int t = 0; t < acc[mi][ni].num_elements; t++)
                        acc[mi][ni].x[t] = 1.0f / (1.0f + expf(-acc[mi][ni].x[t]));
                } else if (EPI == 3) {
                    #pragma unroll
                    for (int t = 0; t < acc[mi][ni].num_elements; t++)
                        acc[mi][ni].x[t] = to_tf32(acc[mi][ni].x[t]);
                }
                float* cp = C + (size_t)(by * BM + wm * 32 + mi * 16) * N
                              + bx * BN + wn * 64 + ni * 16;
                wmma::store_matrix_sync(cp, acc[mi][ni], N, wmma::mem_row_major);
            }
        }
    } else {
        // bias+sigmoid: stage half tiles (64 rows) through smem for column map
        float* Cs = smem;
        const int n0 = bx * BN;
        #pragma unroll
        for (int half = 0; half < 2; half++) {
            __syncthreads();
            if ((wm >> 1) == half) {
                const int lm = wm & 1;   // 0..1 within half
                #pragma unroll
                for (int mi = 0; mi < 2; mi++)
                    #pragma unroll
                    for (int ni = 0; ni < 4; ni++)
                        wmma::store_matrix_sync(Cs + (lm * 32 + mi * 16) * C_LD + wn * 64 + ni * 16,
                                                acc[mi][ni], C_LD, wmma::mem_row_major);
            }
            __syncthreads();
            #pragma unroll
            for (int it = 0; it < 8; it++) {
                const int idx = tid + it * 256;     // 0..2047
                const int r = idx >> 5;
                const int c4 = (idx & 31) * 4;
                float4 vv = *(const float4*)(Cs + r * C_LD + c4);
                const float4 bb = *(const float4*)(bias + n0 + c4);
                vv.x = 1.0f / (1.0f + expf(-(vv.x + bb.x)));
                vv.y = 1.0f / (1.0f + expf(-(vv.y + bb.y)));
                vv.z = 1.0f / (1.0f + expf(-(vv.z + bb.z)));
                vv.w = 1.0f / (1.0f + expf(-(vv.w + bb.w)));
                *(float4*)(C + (size_t)(by * BM + half * 64 + r) * N + n0 + c4) = vv;
            }
        }
    }
}

// ---------------------------------------------------------------------------
// Selective WKV scan. One block per (b,h); y output tf32-rounded (feeds GEMM).
// ---------------------------------------------------------------------------
__global__ __launch_bounds__(256, 4)
void scan_kernel(const float* __restrict__ w, const float* __restrict__ k,
                 const float* __restrict__ v, const float* __restrict__ r,
                 float* __restrict__ y, float* __restrict__ state_out)
{
    const int bh = blockIdx.x;
    const int b  = bh / NHEAD;
    const int h  = bh % NHEAD;
    const int tid = threadIdx.x;
    const int j   = tid & 63;
    const int q   = tid >> 6;

    __shared__ float sh[2][4][64];
    __shared__ float ysh[4][64];

    const size_t base = ((size_t)b * SEQ) * CDIM + (size_t)h * HSIZE;

    const int vec = q;
    const int lane = j;
    const float* pvec = (vec == 0) ? w : (vec == 1) ? k : (vec == 2) ? v : r;

    sh[0][vec][lane] = pvec[base + lane];

    float st[16];
    #pragma unroll
    for (int ii = 0; ii < 16; ii++) st[ii] = 0.0f;

    __syncthreads();

    for (int t = 0; t < SEQ; t++) {
        const int cur = t & 1;
        float pf = 0.0f;
        if (t + 1 < SEQ) pf = pvec[base + (size_t)(t + 1) * CDIM + lane];

        const float vj = sh[cur][2][j];
        float acc = 0.0f;
        #pragma unroll
        for (int ii = 0; ii < 16; ii++) {
            const int i = q * 16 + ii;
            const float wi = sh[cur][0][i];
            const float ki = sh[cur][1][i];
            const float ri = sh[cur][3][i];
            float s = st[ii];
            s = (1.0f - wi) * s + ki * vj;
            st[ii] = s;
            acc = fmaf(ri, s, acc);
        }
        ysh[q][j] = acc;
        __syncthreads();

        sh[cur ^ 1][vec][lane] = pf;
        if (q == 0) {
            float yv = ysh[0][j] + ysh[1][j] + ysh[2][j] + ysh[3][j];
            y[base + (size_t)t * CDIM + j] = to_tf32(yv);
        }
        __syncthreads();
    }

    if (state_out != nullptr) {
        #pragma unroll
        for (int ii = 0; ii < 16; ii++) {
            const int i = q * 16 + ii;
            state_out[(((size_t)b * NHEAD + h) * HSIZE + i) * HSIZE + j] = st[ii];
        }
    }
}

// ---------------------------------------------------------------------------
// Launch
// ---------------------------------------------------------------------------
extern "C" void kernel_launch(void* const* d_in, const int* in_sizes, int n_in,
                              void* d_out, int out_size)
{
    const float* x     = (const float*)d_in[0];
    const float* Wx    = (const float*)d_in[1];
    const float* Ww    = (const float*)d_in[2];
    const float* bw    = (const float*)d_in[3];
    const float* Wk    = (const float*)d_in[4];
    const float* Wv    = (const float*)d_in[5];
    const float* Wr    = (const float*)d_in[6];
    const float* Wo    = (const float*)d_in[7];
    const float* gamma = (const float*)d_in[8];
    const float* beta  = (const float*)d_in[9];
    float* out = (float*)d_out;

    float *xn, *tmp, *w, *k, *v, *r, *y, *wt;
    cudaGetSymbolAddress((void**)&xn,  g_xn);
    cudaGetSymbolAddress((void**)&tmp, g_tmp);
    cudaGetSymbolAddress((void**)&w,   g_w);
    cudaGetSymbolAddress((void**)&k,   g_k);
    cudaGetSymbolAddress((void**)&v,   g_v);
    cudaGetSymbolAddress((void**)&r,   g_r);
    cudaGetSymbolAddress((void**)&y,   g_y);
    cudaGetSymbolAddress((void**)&wt,  g_wt);

    cudaFuncSetAttribute(gemm_wmma<0>, cudaFuncAttributeMaxDynamicSharedMemorySize, SMEM_BYTES);
    cudaFuncSetAttribute(gemm_wmma<1>, cudaFuncAttributeMaxDynamicSharedMemorySize, SMEM_BYTES);
    cudaFuncSetAttribute(gemm_wmma<2>, cudaFuncAttributeMaxDynamicSharedMemorySize, SMEM_BYTES);
    cudaFuncSetAttribute(gemm_wmma<3>, cudaFuncAttributeMaxDynamicSharedMemorySize, SMEM_BYTES);

    const int M = MROWS, N = CDIM, K = CDIM;
    dim3 gg(N / BN, M / BM);   // (16, 128)
    const int RB = (CDIM * CDIM / 4) / 256;   // rounding grid

    // 1. LayerNorm (tf32-rounded output)
    ln_kernel<<<MROWS, 256>>>(x, gamma, beta, xn);

    // 2. Projections — round weight to tf32 (stream-ordered), then GEMM
    round_tf32_kernel<<<RB, 256>>>(Wx, wt);
    gemm_wmma<3><<<gg, 256, SMEM_BYTES>>>(xn,  wt, nullptr, tmp, M, N, K);
    round_tf32_kernel<<<RB, 256>>>(Ww, wt);
    gemm_wmma<2><<<gg, 256, SMEM_BYTES>>>(tmp, wt, bw,      w,   M, N, K);
    round_tf32_kernel<<<RB, 256>>>(Wk, wt);
    gemm_wmma<0><<<gg, 256, SMEM_BYTES>>>(xn,  wt, nullptr, k,   M, N, K);
    round_tf32_kernel<<<RB, 256>>>(Wv, wt);
    gemm_wmma<0><<<gg, 256, SMEM_BYTES>>>(xn,  wt, nullptr, v,   M, N, K);
    round_tf32_kernel<<<RB, 256>>>(Wr, wt);
    gemm_wmma<1><<<gg, 256, SMEM_BYTES>>>(xn,  wt, nullptr, r,   M, N, K);

    // 3. Recurrent scan (y tf32-rounded; final state fp32 into tail of d_out)
    long long n_y = (long long)MROWS * CDIM;
    float* state_ptr = ((long long)out_size > n_y) ? (out + n_y) : nullptr;
    scan_kernel<<<BATCH * NHEAD, 256>>>(w, k, v, r, y, state_ptr);

    // 4. Output projection
    round_tf32_kernel<<<RB, 256>>>(Wo, wt);
    gemm_wmma<0><<<gg, 256, SMEM_BYTES>>>(y, wt, nullptr, out, M, N, K);
}

// round 12
// speedup vs baseline: 1.9083x; 1.1808x over previous
#include <cuda_runtime.h>
#include <cuda_bf16.h>
#include <mma.h>
#include <math.h>
#include <stdint.h>

using namespace nvcuda;

#define BATCH 8
#define SEQ   2048
#define CDIM  2048
#define NHEAD 32
#define HSIZE 64
#define MROWS (BATCH*SEQ)          // 16384

// Scratch buffers (device globals — no runtime allocation allowed)
__device__ float g_xn [(size_t)MROWS * CDIM];
__device__ float g_tmp[(size_t)MROWS * CDIM];
__device__ float g_w  [(size_t)MROWS * CDIM];
__device__ float g_k  [(size_t)MROWS * CDIM];
__device__ float g_v  [(size_t)MROWS * CDIM];
__device__ float g_r  [(size_t)MROWS * CDIM];
__device__ float g_y  [(size_t)MROWS * CDIM];
__device__ float g_wt [(size_t)CDIM * CDIM];   // tf32-rounded weight (reused per GEMM)

// ---------------------------------------------------------------------------
// helpers
// ---------------------------------------------------------------------------
__device__ __forceinline__ uint32_t smem_u32(const void* p) {
    return (uint32_t)__cvta_generic_to_shared(p);
}
__device__ __forceinline__ void cp_async16(uint32_t smem, const void* gmem) {
    asm volatile("cp.async.cg.shared.global [%0], [%1], 16;" :: "r"(smem), "l"(gmem) : "memory");
}
#define CP_COMMIT() asm volatile("cp.async.commit_group;" ::: "memory")
#define CP_WAIT2()  asm volatile("cp.async.wait_group 2;"  ::: "memory")

__device__ __forceinline__ float to_tf32(float f) {
    uint32_t u;
    asm("cvt.rna.tf32.f32 %0, %1;" : "=r"(u) : "f"(f));
    return __uint_as_float(u);
}

// ---------------------------------------------------------------------------
// Round a tensor to tf32 in-memory (weights). 4 elems/thread.
// ---------------------------------------------------------------------------
__global__ void round_tf32_kernel(const float* __restrict__ in, float* __restrict__ out)
{
    const size_t i = ((size_t)blockIdx.x * blockDim.x + threadIdx.x) * 4;
    float4 vv = *(const float4*)(in + i);
    vv.x = to_tf32(vv.x); vv.y = to_tf32(vv.y);
    vv.z = to_tf32(vv.z); vv.w = to_tf32(vv.w);
    *(float4*)(out + i) = vv;
}

// ---------------------------------------------------------------------------
// LayerNorm: one block per row of C=2048, 256 threads. Output tf32-rounded
// (only consumed as GEMM A operand).
// ---------------------------------------------------------------------------
__global__ void ln_kernel(const float* __restrict__ x,
                          const float* __restrict__ gamma,
                          const float* __restrict__ beta,
                          float* __restrict__ out)
{
    const int row = blockIdx.x;
    const int tid = threadIdx.x;
    const float* xr = x + (size_t)row * CDIM;
    float* orow = out + (size_t)row * CDIM;

    float4 a = *(const float4*)(xr + tid * 4);
    float4 b = *(const float4*)(xr + 1024 + tid * 4);

    float s  = a.x + a.y + a.z + a.w + b.x + b.y + b.z + b.w;
    float sq = a.x*a.x + a.y*a.y + a.z*a.z + a.w*a.w
             + b.x*b.x + b.y*b.y + b.z*b.z + b.w*b.w;

    __shared__ float red[2][32];
    #pragma unroll
    for (int o = 16; o > 0; o >>= 1) {
        s  += __shfl_down_sync(0xffffffffu, s,  o);
        sq += __shfl_down_sync(0xffffffffu, sq, o);
    }
    int wid = tid >> 5, lane = tid & 31;
    if (lane == 0) { red[0][wid] = s; red[1][wid] = sq; }
    __syncthreads();
    if (wid == 0) {
        float ss = (lane < 8) ? red[0][lane] : 0.0f;
        float qq = (lane < 8) ? red[1][lane] : 0.0f;
        #pragma unroll
        for (int o = 4; o > 0; o >>= 1) {
            ss += __shfl_down_sync(0xffffffffu, ss, o);
            qq += __shfl_down_sync(0xffffffffu, qq, o);
        }
        if (lane == 0) { red[0][0] = ss; red[1][0] = qq; }
    }
    __syncthreads();
    float mean = red[0][0] * (1.0f / CDIM);
    float var  = red[1][0] * (1.0f / CDIM) - mean * mean;
    float rstd = rsqrtf(var + 1e-5f);

    float4 g0 = *(const float4*)(gamma + tid * 4);
    float4 g1 = *(const float4*)(gamma + 1024 + tid * 4);
    float4 be0 = *(const float4*)(beta + tid * 4);
    float4 be1 = *(const float4*)(beta + 1024 + tid * 4);

    float4 o0, o1;
    o0.x = to_tf32((a.x - mean) * rstd * g0.x + be0.x);
    o0.y = to_tf32((a.y - mean) * rstd * g0.y + be0.y);
    o0.z = to_tf32((a.z - mean) * rstd * g0.z + be0.z);
    o0.w = to_tf32((a.w - mean) * rstd * g0.w + be0.w);
    o1.x = to_tf32((b.x - mean) * rstd * g1.x + be1.x);
    o1.y = to_tf32((b.y - mean) * rstd * g1.y + be1.y);
    o1.z = to_tf32((b.z - mean) * rstd * g1.z + be1.z);
    o1.w = to_tf32((b.w - mean) * rstd * g1.w + be1.w);

    *(float4*)(orow + tid * 4)        = o0;
    *(float4*)(orow + 1024 + tid * 4) = o1;
}

// ---------------------------------------------------------------------------
// WMMA TF32 GEMM: C[M,N] = A[M,K] @ B[K,N]. Operands PRE-ROUNDED to tf32.
// BM=128, BN=128, BK=16, 4-stage cp.async pipeline.
// 4 warps (2x2), warp tile 64x64 = 4x4 wmma m16n16k8 tiles, 2 CTAs/SM.
// EPI: 0=none, 1=sigmoid, 2=bias+sigmoid (smem-staged), 3=round-to-tf32
// ---------------------------------------------------------------------------
#define BM 128
#define BN 128
#define BK 16
#define NSTAGE 4
#define NTHREADS 128
#define A_LD 20            // 16 + 4 pad
#define B_LD 132           // 128 + 4 pad
#define A_FLOATS (BM * A_LD)                 // 2560
#define B_FLOATS (BK * B_LD)                 // 2112
#define STAGE_FLOATS (A_FLOATS + B_FLOATS)   // 4672
#define SMEM_FLOATS (NSTAGE * STAGE_FLOATS)  // 18688
#define C_LD 132
#define SMEM_BYTES (SMEM_FLOATS * 4)         // 74752 (> 128*C_LD*4? no: 67584 < 74752 ok)

template<int EPI>
__global__ void __launch_bounds__(NTHREADS, 2)
gemm_wmma(const float* __restrict__ A, const float* __restrict__ B,
          const float* __restrict__ bias, float* __restrict__ C,
          int M, int N, int K)
{
    extern __shared__ float smem[];
    const int tid = threadIdx.x;
    const int wid = tid >> 5;
    const int bx = blockIdx.x;   // N tile
    const int by = blockIdx.y;   // M tile
    const int NITER = K / BK;    // 128

    const int wm = wid & 1;      // warp row: 64-row slab
    const int wn = wid >> 1;     // warp col: 64-col slab

    const float* Ablk = A + (size_t)(by * BM) * K;
    const float* Bblk = B + (size_t)(bx * BN);

    // per-thread load coordinates: 4 A chunks + 4 B chunks of 16B per stage
    // A: 512 chunks (128 rows x 4 chunks); B: 512 chunks (16 rows x 32 chunks)
    const uint32_t smem_b = smem_u32(smem);

    auto load_stage = [&](int s, int k0) {
        const uint32_t as = smem_b + (uint32_t)(s * STAGE_FLOATS) * 4;
        const uint32_t bs = as + (uint32_t)A_FLOATS * 4;
        #pragma unroll
        for (int c = 0; c < 4; c++) {
            const int ch = tid + c * NTHREADS;       // 0..511
            const int ar = ch >> 2, ac = (ch & 3) * 4;
            cp_async16(as + (uint32_t)(ar * A_LD + ac) * 4, Ablk + (size_t)ar * K + k0 + ac);
        }
        #pragma unroll
        for (int c = 0; c < 4; c++) {
            const int ch = tid + c * NTHREADS;       // 0..511
            const int br = ch >> 5, bc = (ch & 31) * 4;
            cp_async16(bs + (uint32_t)(br * B_LD + bc) * 4, Bblk + (size_t)(k0 + br) * N + bc);
        }
    };

    wmma::fragment<wmma::accumulator, 16, 16, 8, float> acc[4][4];
    #pragma unroll
    for (int mi = 0; mi < 4; mi++)
        #pragma unroll
        for (int ni = 0; ni < 4; ni++)
            wmma::fill_fragment(acc[mi][ni], 0.0f);

    #pragma unroll
    for (int j = 0; j < NSTAGE - 1; j++) { load_stage(j, j * BK); CP_COMMIT(); }

    for (int i = 0; i < NITER; i++) {
        CP_WAIT2();
        __syncthreads();

        if (i + NSTAGE - 1 < NITER)
            load_stage((i + NSTAGE - 1) & (NSTAGE - 1), (i + NSTAGE - 1) * BK);
        CP_COMMIT();

        const int s = i & (NSTAGE - 1);
        const float* As = smem + s * STAGE_FLOATS;
        const float* Bs = As + A_FLOATS;

        #pragma unroll
        for (int ks = 0; ks < 2; ks++) {
            wmma::fragment<wmma::matrix_a, 16, 16, 8, wmma::precision::tf32, wmma::row_major> af[4];
            wmma::fragment<wmma::matrix_b, 16, 16, 8, wmma::precision::tf32, wmma::row_major> bf[4];
            #pragma unroll
            for (int mi = 0; mi < 4; mi++)
                wmma::load_matrix_sync(af[mi], As + (wm * 64 + mi * 16) * A_LD + ks * 8, A_LD);
            #pragma unroll
            for (int ni = 0; ni < 4; ni++)
                wmma::load_matrix_sync(bf[ni], Bs + (ks * 8) * B_LD + wn * 64 + ni * 16, B_LD);
            // operands pre-rounded to tf32 in memory; no cvt needed.
            #pragma unroll
            for (int mi = 0; mi < 4; mi++)
                #pragma unroll
                for (int ni = 0; ni < 4; ni++)
                    wmma::mma_sync(acc[mi][ni], af[mi], bf[ni], acc[mi][ni]);
        }
    }

    if (EPI != 2) {
        // direct-from-fragment epilogue (elementwise ops are position-free)
        #pragma unroll
        for (int mi = 0; mi < 4; mi++) {
            #pragma unroll
            for (int ni = 0; ni < 4; ni++) {
                if (EPI == 1) {
                    #pragma unroll
                    for (int t = 0; t < acc[mi][ni].num_elements; t++)
                        acc[mi][ni].x[t] = 1.0f / (1.0f + expf(-acc[mi][ni].x[t]));
                } else if (EPI == 3) {
                    #pragma unroll
                    for (int t = 0; t < acc[mi][ni].num_elements; t++)
                        acc[mi][ni].x[t] = to_tf32(acc[mi][ni].x[t]);
                }
                float* cp = C + (size_t)(by * BM + wm * 64 + mi * 16) * N
                              + bx * BN + wn * 64 + ni * 16;
                wmma::store_matrix_sync(cp, acc[mi][ni], N, wmma::mem_row_major);
            }
        }
    } else {
        // bias+sigmoid: stage full 128x128 tile through smem (67584B < SMEM_BYTES)
        float* Cs = smem;
        const int n0 = bx * BN;
        __syncthreads();
        #pragma unroll
        for (int mi = 0; mi < 4; mi++)
            #pragma unroll
            for (int ni = 0; ni < 4; ni++)
                wmma::store_matrix_sync(Cs + (wm * 64 + mi * 16) * C_LD + wn * 64 + ni * 16,
                                        acc[mi][ni], C_LD, wmma::mem_row_major);
        __syncthreads();
        #pragma unroll
        for (int it = 0; it < 32; it++) {
            const int idx = tid + it * NTHREADS;   // 0..4095
            const int r = idx >> 5;
            const int c4 = (idx & 31) * 4;
            float4 vv = *(const float4*)(Cs + r * C_LD + c4);
            const float4 bb = *(const float4*)(bias + n0 + c4);
            vv.x = 1.0f / (1.0f + expf(-(vv.x + bb.x)));
            vv.y = 1.0f / (1.0f + expf(-(vv.y + bb.y)));
            vv.z = 1.0f / (1.0f + expf(-(vv.z + bb.z)));
            vv.w = 1.0f / (1.0f + expf(-(vv.w + bb.w)));
            *(float4*)(C + (size_t)(by * BM + r) * N + n0 + c4) = vv;
        }
    }
}

// ---------------------------------------------------------------------------
// Selective WKV scan. One block per (b,h); y output tf32-rounded (feeds GEMM).
// ---------------------------------------------------------------------------
__global__ __launch_bounds__(256, 4)
void scan_kernel(const float* __restrict__ w, const float* __restrict__ k,
                 const float* __restrict__ v, const float* __restrict__ r,
                 float* __restrict__ y, float* __restrict__ state_out)
{
    const int bh = blockIdx.x;
    const int b  = bh / NHEAD;
    const int h  = bh % NHEAD;
    const int tid = threadIdx.x;
    const int j   = tid & 63;
    const int q   = tid >> 6;

    __shared__ float sh[2][4][64];
    __shared__ float ysh[4][64];

    const size_t base = ((size_t)b * SEQ) * CDIM + (size_t)h * HSIZE;

    const int vec = q;
    const int lane = j;
    const float* pvec = (vec == 0) ? w : (vec == 1) ? k : (vec == 2) ? v : r;

    sh[0][vec][lane] = pvec[base + lane];

    float st[16];
    #pragma unroll
    for (int ii = 0; ii < 16; ii++) st[ii] = 0.0f;

    __syncthreads();

    for (int t = 0; t < SEQ; t++) {
        const int cur = t & 1;
        float pf = 0.0f;
        if (t + 1 < SEQ) pf = pvec[base + (size_t)(t + 1) * CDIM + lane];

        const float vj = sh[cur][2][j];
        float acc = 0.0f;
        #pragma unroll
        for (int ii = 0; ii < 16; ii++) {
            const int i = q * 16 + ii;
            const float wi = sh[cur][0][i];
            const float ki = sh[cur][1][i];
            const float ri = sh[cur][3][i];
            float s = st[ii];
            s = (1.0f - wi) * s + ki * vj;
            st[ii] = s;
            acc = fmaf(ri, s, acc);
        }
        ysh[q][j] = acc;
        __syncthreads();

        sh[cur ^ 1][vec][lane] = pf;
        if (q == 0) {
            float yv = ysh[0][j] + ysh[1][j] + ysh[2][j] + ysh[3][j];
            y[base + (size_t)t * CDIM + j] = to_tf32(yv);
        }
        __syncthreads();
    }

    if (state_out != nullptr) {
        #pragma unroll
        for (int ii = 0; ii < 16; ii++) {
            const int i = q * 16 + ii;
            state_out[(((size_t)b * NHEAD + h) * HSIZE + i) * HSIZE + j] = st[ii];
        }
    }
}

// ---------------------------------------------------------------------------
// Launch
// ---------------------------------------------------------------------------
extern "C" void kernel_launch(void* const* d_in, const int* in_sizes, int n_in,
                              void* d_out, int out_size)
{
    const float* x     = (const float*)d_in[0];
    const float* Wx    = (const float*)d_in[1];
    const float* Ww    = (const float*)d_in[2];
    const float* bw    = (const float*)d_in[3];
    const float* Wk    = (const float*)d_in[4];
    const float* Wv    = (const float*)d_in[5];
    const float* Wr    = (const float*)d_in[6];
    const float* Wo    = (const float*)d_in[7];
    const float* gamma = (const float*)d_in[8];
    const float* beta  = (const float*)d_in[9];
    float* out = (float*)d_out;

    float *xn, *tmp, *w, *k, *v, *r, *y, *wt;
    cudaGetSymbolAddress((void**)&xn,  g_xn);
    cudaGetSymbolAddress((void**)&tmp, g_tmp);
    cudaGetSymbolAddress((void**)&w,   g_w);
    cudaGetSymbolAddress((void**)&k,   g_k);
    cudaGetSymbolAddress((void**)&v,   g_v);
    cudaGetSymbolAddress((void**)&r,   g_r);
    cudaGetSymbolAddress((void**)&y,   g_y);
    cudaGetSymbolAddress((void**)&wt,  g_wt);

    cudaFuncSetAttribute(gemm_wmma<0>, cudaFuncAttributeMaxDynamicSharedMemorySize, SMEM_BYTES);
    cudaFuncSetAttribute(gemm_wmma<1>, cudaFuncAttributeMaxDynamicSharedMemorySize, SMEM_BYTES);
    cudaFuncSetAttribute(gemm_wmma<2>, cudaFuncAttributeMaxDynamicSharedMemorySize, SMEM_BYTES);
    cudaFuncSetAttribute(gemm_wmma<3>, cudaFuncAttributeMaxDynamicSharedMemorySize, SMEM_BYTES);

    const int M = MROWS, N = CDIM, K = CDIM;
    dim3 gg(N / BN, M / BM);   // (16, 128)
    const int RB = (CDIM * CDIM / 4) / 256;   // rounding grid

    // 1. LayerNorm (tf32-rounded output)
    ln_kernel<<<MROWS, 256>>>(x, gamma, beta, xn);

    // 2. Projections — round weight to tf32 (stream-ordered), then GEMM
    round_tf32_kernel<<<RB, 256>>>(Wx, wt);
    gemm_wmma<3><<<gg, NTHREADS, SMEM_BYTES>>>(xn,  wt, nullptr, tmp, M, N, K);
    round_tf32_kernel<<<RB, 256>>>(Ww, wt);
    gemm_wmma<2><<<gg, NTHREADS, SMEM_BYTES>>>(tmp, wt, bw,      w,   M, N, K);
    round_tf32_kernel<<<RB, 256>>>(Wk, wt);
    gemm_wmma<0><<<gg, NTHREADS, SMEM_BYTES>>>(xn,  wt, nullptr, k,   M, N, K);
    round_tf32_kernel<<<RB, 256>>>(Wv, wt);
    gemm_wmma<0><<<gg, NTHREADS, SMEM_BYTES>>>(xn,  wt, nullptr, v,   M, N, K);
    round_tf32_kernel<<<RB, 256>>>(Wr, wt);
    gemm_wmma<1><<<gg, NTHREADS, SMEM_BYTES>>>(xn,  wt, nullptr, r,   M, N, K);

    // 3. Recurrent scan (y tf32-rounded; final state fp32 into tail of d_out)
    long long n_y = (long long)MROWS * CDIM;
    float* state_ptr = ((long long)out_size > n_y) ? (out + n_y) : nullptr;
    scan_kernel<<<BATCH * NHEAD, 256>>>(w, k, v, r, y, state_ptr);

    // 4. Output projection
    round_tf32_kernel<<<RB, 256>>>(Wo, wt);
    gemm_wmma<0><<<gg, NTHREADS, SMEM_BYTES>>>(y, wt, nullptr, out, M, N, K);
}

// round 13
// speedup vs baseline: 4.0322x; 2.1129x over previous
#include <cuda_runtime.h>
#include <cuda_bf16.h>
#include <math.h>
#include <stdint.h>

#define BATCH 8
#define SEQ   2048
#define CDIM  2048
#define NHEAD 32
#define HSIZE 64
#define MROWS (BATCH*SEQ)          // 16384

// Scratch buffers (device globals — no runtime allocation allowed)
__device__ float g_xn [(size_t)MROWS * CDIM];
__device__ float g_tmp[(size_t)MROWS * CDIM];
__device__ float g_w  [(size_t)MROWS * CDIM];
__device__ float g_k  [(size_t)MROWS * CDIM];
__device__ float g_v  [(size_t)MROWS * CDIM];
__device__ float g_r  [(size_t)MROWS * CDIM];
__device__ float g_y  [(size_t)MROWS * CDIM];
__device__ float g_wt [(size_t)CDIM * CDIM];   // transposed + tf32-rounded weight [N,K]

// ---------------------------------------------------------------------------
// helpers
// ---------------------------------------------------------------------------
__device__ __forceinline__ uint32_t smem_u32(const void* p) {
    return (uint32_t)__cvta_generic_to_shared(p);
}
__device__ __forceinline__ void cp_async16(uint32_t smem, const void* gmem) {
    asm volatile("cp.async.cg.shared.global [%0], [%1], 16;" :: "r"(smem), "l"(gmem) : "memory");
}
#define CP_COMMIT() asm volatile("cp.async.commit_group;" ::: "memory")
#define CP_WAIT2()  asm volatile("cp.async.wait_group 2;"  ::: "memory")

__device__ __forceinline__ float to_tf32(float f) {
    uint32_t u;
    asm("cvt.rna.tf32.f32 %0, %1;" : "=r"(u) : "f"(f));
    return __uint_as_float(u);
}

#define LDSM_X4(r0, r1, r2, r3, addr) \
    asm volatile("ldmatrix.sync.aligned.m8n8.x4.shared.b16 {%0,%1,%2,%3}, [%4];" \
                 : "=r"(r0), "=r"(r1), "=r"(r2), "=r"(r3) : "r"(addr))

#define MMA_TF32(d, a, b0v, b1v) \
    asm volatile("mma.sync.aligned.m16n8k8.row.col.f32.tf32.tf32.f32 " \
                 "{%0,%1,%2,%3}, {%4,%5,%6,%7}, {%8,%9}, {%0,%1,%2,%3};" \
                 : "+f"(d[0]), "+f"(d[1]), "+f"(d[2]), "+f"(d[3]) \
                 : "r"(a[0]), "r"(a[1]), "r"(a[2]), "r"(a[3]), "r"(b0v), "r"(b1v))

// ---------------------------------------------------------------------------
// Weight prep: transpose [K,N] -> [N,K] with tf32 rounding.
// ---------------------------------------------------------------------------
__global__ void wprep_kernel(const float* __restrict__ in, float* __restrict__ out)
{
    __shared__ float t[32][33];
    const int bx = blockIdx.x * 32;   // n
    const int by = blockIdx.y * 32;   // k
    const int x = bx + threadIdx.x;
    #pragma unroll
    for (int dy = 0; dy < 32; dy += 8)
        t[threadIdx.y + dy][threadIdx.x] = in[(size_t)(by + threadIdx.y + dy) * CDIM + x];
    __syncthreads();
    const int ok = by + threadIdx.x;
    #pragma unroll
    for (int dy = 0; dy < 32; dy += 8)
        out[(size_t)(bx + threadIdx.y + dy) * CDIM + ok] = to_tf32(t[threadIdx.x][threadIdx.y + dy]);
}

// ---------------------------------------------------------------------------
// LayerNorm: one block per row of C=2048, 256 threads; output tf32-rounded.
// ---------------------------------------------------------------------------
__global__ void ln_kernel(const float* __restrict__ x,
                          const float* __restrict__ gamma,
                          const float* __restrict__ beta,
                          float* __restrict__ out)
{
    const int row = blockIdx.x;
    const int tid = threadIdx.x;
    const float* xr = x + (size_t)row * CDIM;
    float* orow = out + (size_t)row * CDIM;

    float4 a = *(const float4*)(xr + tid * 4);
    float4 b = *(const float4*)(xr + 1024 + tid * 4);

    float s  = a.x + a.y + a.z + a.w + b.x + b.y + b.z + b.w;
    float sq = a.x*a.x + a.y*a.y + a.z*a.z + a.w*a.w
             + b.x*b.x + b.y*b.y + b.z*b.z + b.w*b.w;

    __shared__ float red[2][32];
    #pragma unroll
    for (int o = 16; o > 0; o >>= 1) {
        s  += __shfl_down_sync(0xffffffffu, s,  o);
        sq += __shfl_down_sync(0xffffffffu, sq, o);
    }
    int wid = tid >> 5, lane = tid & 31;
    if (lane == 0) { red[0][wid] = s; red[1][wid] = sq; }
    __syncthreads();
    if (wid == 0) {
        float ss = (lane < 8) ? red[0][lane] : 0.0f;
        float qq = (lane < 8) ? red[1][lane] : 0.0f;
        #pragma unroll
        for (int o = 4; o > 0; o >>= 1) {
            ss += __shfl_down_sync(0xffffffffu, ss, o);
            qq += __shfl_down_sync(0xffffffffu, qq, o);
        }
        if (lane == 0) { red[0][0] = ss; red[1][0] = qq; }
    }
    __syncthreads();
    float mean = red[0][0] * (1.0f / CDIM);
    float var  = red[1][0] * (1.0f / CDIM) - mean * mean;
    float rstd = rsqrtf(var + 1e-5f);

    float4 g0 = *(const float4*)(gamma + tid * 4);
    float4 g1 = *(const float4*)(gamma + 1024 + tid * 4);
    float4 be0 = *(const float4*)(beta + tid * 4);
    float4 be1 = *(const float4*)(beta + 1024 + tid * 4);

    float4 o0, o1;
    o0.x = to_tf32((a.x - mean) * rstd * g0.x + be0.x);
    o0.y = to_tf32((a.y - mean) * rstd * g0.y + be0.y);
    o0.z = to_tf32((a.z - mean) * rstd * g0.z + be0.z);
    o0.w = to_tf32((a.w - mean) * rstd * g0.w + be0.w);
    o1.x = to_tf32((b.x - mean) * rstd * g1.x + be1.x);
    o1.y = to_tf32((b.y - mean) * rstd * g1.y + be1.y);
    o1.z = to_tf32((b.z - mean) * rstd * g1.z + be1.z);
    o1.w = to_tf32((b.w - mean) * rstd * g1.w + be1.w);

    *(float4*)(orow + tid * 4)        = o0;
    *(float4*)(orow + 1024 + tid * 4) = o1;
}

// ---------------------------------------------------------------------------
// Raw mma.sync TF32 GEMM: C[M,N] = A[M,K] @ Bt[N,K]^T, both K-major, both
// PRE-ROUNDED to tf32 in memory. ldmatrix.b16 fragment loads (bit-exact for
// tf32 when operands are K-major).
// Block 128x128, BK=16, 4 warps (2x2) with 64x64 warp tiles, 4-stage cp.async,
// 2 CTAs/SM, direct-from-register epilogue.
// smem tile layout: row-major 64B rows (16 floats), 16B chunks XOR-swizzled:
//   phys_chunk = k4 ^ ((row>>1)&3)  -> 8 consecutive rows hit 8 distinct 16B
//   slots per 128B: conflict-free for both cp.async stores and ldmatrix.
// EPI: 0=none, 1=sigmoid, 2=bias+sigmoid, 3=round-to-tf32
// ---------------------------------------------------------------------------
#define BM 128
#define BN 128
#define BK 16
#define NSTAGE 4
#define NTHREADS 128
#define A_BYTES (BM * BK * 4)                 // 8192
#define STAGE_BYTES (2 * A_BYTES)             // 16384
#define SMEM_BYTES (NSTAGE * STAGE_BYTES)     // 65536

template<int EPI>
__global__ void __launch_bounds__(NTHREADS, 2)
gemm_mma(const float* __restrict__ A, const float* __restrict__ Bt,
         const float* __restrict__ bias, float* __restrict__ C,
         int M, int N, int K)
{
    extern __shared__ float smem[];
    const int tid  = threadIdx.x;
    const int wid  = tid >> 5;
    const int lane = tid & 31;
    const int bx = blockIdx.x;   // N tile
    const int by = blockIdx.y;   // M tile
    const int NITER = K / BK;    // 128

    const int wm = wid & 1;      // warp row: 64-row slab
    const int wn = wid >> 1;     // warp col: 64-col slab

    const float* Ablk = A  + (size_t)(by * BM) * K;
    const float* Bblk = Bt + (size_t)(bx * BN) * K;

    const uint32_t smem_b = smem_u32(smem);

    // ---- cp.async coordinates: 4 A-chunks + 4 B-chunks of 16B per thread ----
    auto load_stage = [&](int s, int k0) {
        const uint32_t sb = smem_b + (uint32_t)s * STAGE_BYTES;
        #pragma unroll
        for (int c = 0; c < 4; c++) {
            const int ch = tid + c * NTHREADS;       // 0..511
            const int row = ch >> 2, k4 = ch & 3;
            const int phys = k4 ^ ((row >> 1) & 3);
            cp_async16(sb + (uint32_t)(row * 64 + phys * 16),
                       Ablk + (size_t)row * K + k0 + k4 * 4);
        }
        #pragma unroll
        for (int c = 0; c < 4; c++) {
            const int ch = tid + c * NTHREADS;
            const int row = ch >> 2, k4 = ch & 3;
            const int phys = k4 ^ ((row >> 1) & 3);
            cp_async16(sb + (uint32_t)(A_BYTES + row * 64 + phys * 16),
                       Bblk + (size_t)row * K + k0 + k4 * 4);
        }
    };

    // ---- ldmatrix per-thread offsets (kh=0); kh=1 is addr ^ 32 ----
    // A: x4 tiles: t0 rows+0 kc+0 | t1 rows+8 kc+0 | t2 rows+0 kc+1 | t3 rows+8 kc+1
    // B: x4 tiles: t0 rows+0 kc+0 | t1 rows+0 kc+1 | t2 rows+8 kc+0 | t3 rows+8 kc+1
    const int ltile = lane >> 3, lrit = lane & 7;
    uint32_t aoff[4], boff[4];
    #pragma unroll
    for (int mi = 0; mi < 4; mi++) {
        const int row = wm * 64 + mi * 16 + ((ltile & 1) << 3) + lrit;
        const int kc  = ltile >> 1;
        const int phys = kc ^ ((row >> 1) & 3);
        aoff[mi] = (uint32_t)(row * 64 + phys * 16);
    }
    #pragma unroll
    for (int nj = 0; nj < 4; nj++) {
        const int row = wn * 64 + nj * 16 + ((ltile >> 1) << 3) + lrit;
        const int kc  = ltile & 1;
        const int phys = kc ^ ((row >> 1) & 3);
        boff[nj] = (uint32_t)(A_BYTES + row * 64 + phys * 16);
    }

    float acc[4][8][4];
    #pragma unroll
    for (int mi = 0; mi < 4; mi++)
        #pragma unroll
        for (int n8 = 0; n8 < 8; n8++)
            #pragma unroll
            for (int t = 0; t < 4; t++) acc[mi][n8][t] = 0.0f;

    #pragma unroll
    for (int j = 0; j < NSTAGE - 1; j++) { load_stage(j, j * BK); CP_COMMIT(); }

    for (int i = 0; i < NITER; i++) {
        CP_WAIT2();
        __syncthreads();

        if (i + NSTAGE - 1 < NITER)
            load_stage((i + NSTAGE - 1) & (NSTAGE - 1), (i + NSTAGE - 1) * BK);
        CP_COMMIT();

        const uint32_t sb = smem_b + (uint32_t)(i & (NSTAGE - 1)) * STAGE_BYTES;

        #pragma unroll
        for (int kh = 0; kh < 2; kh++) {
            const uint32_t kx = kh ? 32u : 0u;
            uint32_t af[4][4], bf[4][4];
            #pragma unroll
            for (int mi = 0; mi < 4; mi++)
                LDSM_X4(af[mi][0], af[mi][1], af[mi][2], af[mi][3], sb + (aoff[mi] ^ kx));
            #pragma unroll
            for (int nj = 0; nj < 4; nj++)
                LDSM_X4(bf[nj][0], bf[nj][1], bf[nj][2], bf[nj][3], sb + (boff[nj] ^ kx));
            #pragma unroll
            for (int mi = 0; mi < 4; mi++)
                #pragma unroll
                for (int n8 = 0; n8 < 8; n8++)
                    MMA_TF32(acc[mi][n8], af[mi], bf[n8 >> 1][(n8 & 1) * 2],
                             bf[n8 >> 1][(n8 & 1) * 2 + 1]);
        }
    }

    // ---- direct-from-register epilogue ----
    // acc tile m16n8: thread holds (g,2l),(g,2l+1),(g+8,2l),(g+8,2l+1)
    const int g = lane >> 2, l = lane & 3;
    #pragma unroll
    for (int mi = 0; mi < 4; mi++) {
        const int r0 = by * BM + wm * 64 + mi * 16 + g;
        #pragma unroll
        for (int n8 = 0; n8 < 8; n8++) {
            const int col = bx * BN + wn * 64 + n8 * 8 + l * 2;
            float c0 = acc[mi][n8][0], c1 = acc[mi][n8][1];
            float c2 = acc[mi][n8][2], c3 = acc[mi][n8][3];
            if (EPI == 2) {
                const float2 bb = *(const float2*)(bias + col);
                c0 += bb.x; c1 += bb.y; c2 += bb.x; c3 += bb.y;
            }
            if (EPI == 1 || EPI == 2) {
                c0 = 1.0f / (1.0f + expf(-c0));
                c1 = 1.0f / (1.0f + expf(-c1));
                c2 = 1.0f / (1.0f + expf(-c2));
                c3 = 1.0f / (1.0f + expf(-c3));
            }
            if (EPI == 3) {
                c0 = to_tf32(c0); c1 = to_tf32(c1);
                c2 = to_tf32(c2); c3 = to_tf32(c3);
            }
            *(float2*)(C + (size_t)r0 * N + col)       = make_float2(c0, c1);
            *(float2*)(C + (size_t)(r0 + 8) * N + col) = make_float2(c2, c3);
        }
    }
}

// ---------------------------------------------------------------------------
// Selective WKV scan. One block per (b,h); y output tf32-rounded (feeds GEMM).
// ---------------------------------------------------------------------------
__global__ __launch_bounds__(256, 4)
void scan_kernel(const float* __restrict__ w, const float* __restrict__ k,
                 const float* __restrict__ v, const float* __restrict__ r,
                 float* __restrict__ y, float* __restrict__ state_out)
{
    const int bh = blockIdx.x;
    const int b  = bh / NHEAD;
    const int h  = bh % NHEAD;
    const int tid = threadIdx.x;
    const int j   = tid & 63;
    const int q   = tid >> 6;

    __shared__ float sh[2][4][64];
    __shared__ float ysh[4][64];

    const size_t base = ((size_t)b * SEQ) * CDIM + (size_t)h * HSIZE;

    const int vec = q;
    const int lane = j;
    const float* pvec = (vec == 0) ? w : (vec == 1) ? k : (vec == 2) ? v : r;

    sh[0][vec][lane] = pvec[base + lane];

    float st[16];
    #pragma unroll
    for (int ii = 0; ii < 16; ii++) st[ii] = 0.0f;

    __syncthreads();

    for (int t = 0; t < SEQ; t++) {
        const int cur = t & 1;
        float pf = 0.0f;
        if (t + 1 < SEQ) pf = pvec[base + (size_t)(t + 1) * CDIM + lane];

        const float vj = sh[cur][2][j];
        float acc = 0.0f;
        #pragma unroll
        for (int ii = 0; ii < 16; ii++) {
            const int i = q * 16 + ii;
            const float wi = sh[cur][0][i];
            const float ki = sh[cur][1][i];
            const float ri = sh[cur][3][i];
            float s = st[ii];
            s = (1.0f - wi) * s + ki * vj;
            st[ii] = s;
            acc = fmaf(ri, s, acc);
        }
        ysh[q][j] = acc;
        __syncthreads();

        sh[cur ^ 1][vec][lane] = pf;
        if (q == 0) {
            float yv = ysh[0][j] + ysh[1][j] + ysh[2][j] + ysh[3][j];
            y[base + (size_t)t * CDIM + j] = to_tf32(yv);
        }
        __syncthreads();
    }

    if (state_out != nullptr) {
        #pragma unroll
        for (int ii = 0; ii < 16; ii++) {
            const int i = q * 16 + ii;
            state_out[(((size_t)b * NHEAD + h) * HSIZE + i) * HSIZE + j] = st[ii];
        }
    }
}

// ---------------------------------------------------------------------------
// Launch
// ---------------------------------------------------------------------------
extern "C" void kernel_launch(void* const* d_in, const int* in_sizes, int n_in,
                              void* d_out, int out_size)
{
    const float* x     = (const float*)d_in[0];
    const float* Wx    = (const float*)d_in[1];
    const float* Ww    = (const float*)d_in[2];
    const float* bw    = (const float*)d_in[3];
    const float* Wk    = (const float*)d_in[4];
    const float* Wv    = (const float*)d_in[5];
    const float* Wr    = (const float*)d_in[6];
    const float* Wo    = (const float*)d_in[7];
    const float* gamma = (const float*)d_in[8];
    const float* beta  = (const float*)d_in[9];
    float* out = (float*)d_out;

    float *xn, *tmp, *w, *k, *v, *r, *y, *wt;
    cudaGetSymbolAddress((void**)&xn,  g_xn);
    cudaGetSymbolAddress((void**)&tmp, g_tmp);
    cudaGetSymbolAddress((void**)&w,   g_w);
    cudaGetSymbolAddress((void**)&k,   g_k);
    cudaGetSymbolAddress((void**)&v,   g_v);
    cudaGetSymbolAddress((void**)&r,   g_r);
    cudaGetSymbolAddress((void**)&y,   g_y);
    cudaGetSymbolAddress((void**)&wt,  g_wt);

    cudaFuncSetAttribute(gemm_mma<0>, cudaFuncAttributeMaxDynamicSharedMemorySize, SMEM_BYTES);
    cudaFuncSetAttribute(gemm_mma<1>, cudaFuncAttributeMaxDynamicSharedMemorySize, SMEM_BYTES);
    cudaFuncSetAttribute(gemm_mma<2>, cudaFuncAttributeMaxDynamicSharedMemorySize, SMEM_BYTES);
    cudaFuncSetAttribute(gemm_mma<3>, cudaFuncAttributeMaxDynamicSharedMemorySize, SMEM_BYTES);

    const int M = MROWS, N = CDIM, K = CDIM;
    dim3 gg(N / BN, M / BM);   // (16, 128)
    dim3 tg(64, 64);
    dim3 tb(32, 8);

    // 1. LayerNorm (tf32-rounded output)
    ln_kernel<<<MROWS, 256>>>(x, gamma, beta, xn);

    // 2. Projections — transpose+round weight (stream-ordered), then GEMM
    wprep_kernel<<<tg, tb>>>(Wx, wt);
    gemm_mma<3><<<gg, NTHREADS, SMEM_BYTES>>>(xn,  wt, nullptr, tmp, M, N, K);
    wprep_kernel<<<tg, tb>>>(Ww, wt);
    gemm_mma<2><<<gg, NTHREADS, SMEM_BYTES>>>(tmp, wt, bw,      w,   M, N, K);
    wprep_kernel<<<tg, tb>>>(Wk, wt);
    gemm_mma<0><<<gg, NTHREADS, SMEM_BYTES>>>(xn,  wt, nullptr, k,   M, N, K);
    wprep_kernel<<<tg, tb>>>(Wv, wt);
    gemm_mma<0><<<gg, NTHREADS, SMEM_BYTES>>>(xn,  wt, nullptr, v,   M, N, K);
    wprep_kernel<<<tg, tb>>>(Wr, wt);
    gemm_mma<1><<<gg, NTHREADS, SMEM_BYTES>>>(xn,  wt, nullptr, r,   M, N, K);

    // 3. Recurrent scan (y tf32-rounded; final state fp32 into tail of d_out)
    long long n_y = (long long)MROWS * CDIM;
    float* state_ptr = ((long long)out_size > n_y) ? (out + n_y) : nullptr;
    scan_kernel<<<BATCH * NHEAD, 256>>>(w, k, v, r, y, state_ptr);

    // 4. Output projection
    wprep_kernel<<<tg, tb>>>(Wo, wt);
    gemm_mma<0><<<gg, NTHREADS, SMEM_BYTES>>>(y, wt, nullptr, out, M, N, K);
}